// round 3
// baseline (speedup 1.0000x reference)
#include <cuda_runtime.h>
#include <cuda_fp16.h>

#define N_NODES 50000
#define HF 128          // H*F
#define H_HEADS 4
#define NODES_PER_BLK 32
#define E_MAX 1000000
#define DEG_CAP 64      // smem cache capacity per node (avg deg ~16, Poisson max ~50)
#define SCAN_BLK 1024
#define SCAN_PER ((N_NODES + SCAN_BLK - 1) / SCAN_BLK)

// ---------------- scratch (static device globals; no allocation) ----------------
__device__ __half g_zh[N_NODES * HF];      // z in half (gather path)
__device__ float  g_acc1[N_NODES * HF];    // layer-1 h (base, then elu'd result)
__device__ float  g_acc2[N_NODES * HF];    // layer-2 base (residual+bias)
__device__ float  g_el[N_NODES * H_HEADS];
__device__ float  g_er[N_NODES * H_HEADS];
__device__ int    g_deg[N_NODES];
__device__ int    g_rowptr[N_NODES];
__device__ int    g_cursor[N_NODES];
__device__ int    g_csr_src[E_MAX];

__device__ __forceinline__ float leaky(float v) { return v > 0.f ? v : 0.2f * v; }
__device__ __forceinline__ float elu(float v)   { return v > 0.f ? v : (__expf(v) - 1.f); }

// ---------------- CSR build ----------------
__global__ void zero_deg_kernel(int* deg) {
    int i = blockIdx.x * blockDim.x + threadIdx.x;
    if (i < N_NODES) deg[i] = 0;
}

__global__ void hist_kernel(const int* __restrict__ dst, int E, int* __restrict__ deg) {
    int i = blockIdx.x * blockDim.x + threadIdx.x;
    if (i < E) atomicAdd(&deg[dst[i]], 1);
}

// single-block exclusive scan: thread t owns a contiguous chunk of SCAN_PER nodes
__global__ __launch_bounds__(SCAN_BLK)
void scan_kernel(const int* __restrict__ deg,
                 int* __restrict__ rowptr, int* __restrict__ cursor)
{
    __shared__ int sm[SCAN_BLK];
    const int tid = threadIdx.x;
    const int b = tid * SCAN_PER;
    const int e = min(b + SCAN_PER, N_NODES);

    int local = 0;
    for (int k = b; k < e; k++) local += deg[k];
    sm[tid] = local;
    __syncthreads();
    #pragma unroll
    for (int off = 1; off < SCAN_BLK; off <<= 1) {
        int t = (tid >= off) ? sm[tid - off] : 0;
        __syncthreads();
        sm[tid] += t;
        __syncthreads();
    }
    int run = sm[tid] - local;   // exclusive prefix
    for (int k = b; k < e; k++) {
        rowptr[k] = run;
        cursor[k] = run;
        run += deg[k];
    }
}

__global__ void fill_kernel(const int* __restrict__ src, const int* __restrict__ dst, int E,
                            int* __restrict__ cursor, int* __restrict__ csr_src) {
    int i = blockIdx.x * blockDim.x + threadIdx.x;
    if (i >= E) return;
    int pos = atomicAdd(&cursor[dst[i]], 1);
    csr_src[pos] = src[i];
}

// ---------------- K1: z = x @ W (half out) ; el/er ; base = residual + bias ----------------
__global__ __launch_bounds__(128)
void gemm_attn_kernel(const float* __restrict__ x,
                      const float* __restrict__ W,
                      const float* __restrict__ al,
                      const float* __restrict__ ar,
                      const float* __restrict__ bias,
                      __half* __restrict__ zh,
                      float* __restrict__ base,
                      float* __restrict__ el,
                      float* __restrict__ er)
{
    __shared__ float xs[NODES_PER_BLK * HF];  // 16 KB
    const int j  = threadIdx.x;               // 0..127 output column
    const int n0 = blockIdx.x * NODES_PER_BLK;

    #pragma unroll
    for (int nn = 0; nn < NODES_PER_BLK; nn++) {
        int n = n0 + nn;
        xs[nn * HF + j] = (n < N_NODES) ? x[n * HF + j] : 0.f;
    }
    __syncthreads();

    float sum[NODES_PER_BLK];
    #pragma unroll
    for (int nn = 0; nn < NODES_PER_BLK; nn++) sum[nn] = 0.f;

    for (int k = 0; k < HF; k += 4) {
        float w0 = W[(k + 0) * HF + j];
        float w1 = W[(k + 1) * HF + j];
        float w2 = W[(k + 2) * HF + j];
        float w3 = W[(k + 3) * HF + j];
        #pragma unroll
        for (int nn = 0; nn < NODES_PER_BLK; nn++) {
            float4 xv = *reinterpret_cast<const float4*>(&xs[nn * HF + k]);
            sum[nn] += xv.x * w0 + xv.y * w1 + xv.z * w2 + xv.w * w3;
        }
    }

    const float alj = al[j], arj = ar[j], bj = bias[j];
    const int h = j >> 5, f = j & 31;

    #pragma unroll
    for (int nn = 0; nn < NODES_PER_BLK; nn++) {
        int n = n0 + nn;
        if (n >= N_NODES) break;
        zh[n * HF + j]   = __float2half_rn(sum[nn]);
        base[n * HF + j] = xs[nn * HF + j] + bj;
        float pl = sum[nn] * alj;
        float pr = sum[nn] * arj;
        #pragma unroll
        for (int off = 16; off; off >>= 1) {
            pl += __shfl_down_sync(0xffffffffu, pl, off);
            pr += __shfl_down_sync(0xffffffffu, pr, off);
        }
        if (f == 0) {
            el[n * H_HEADS + h] = pl;
            er[n * H_HEADS + h] = pr;
        }
    }
}

// ---------------- fused softmax + aggregate, one warp per node, no atomics ----------------
// MODE 0: layer-1 epilogue -> elu(acc) stored to hio (becomes layer-2 input)
// MODE 1: layer-2 epilogue -> head-mean + projection, writes out[n] only
template <int MODE>
__global__ __launch_bounds__(256)
void gat_aggregate_kernel(const int* __restrict__ rowptr, const int* __restrict__ deg,
                          const int* __restrict__ csr_src,
                          const float* __restrict__ el, const float* __restrict__ er,
                          const __half* __restrict__ zh,
                          float* __restrict__ hio,          // base in, result out (MODE 0)
                          const float* __restrict__ Wp, const float* __restrict__ bp,
                          float* __restrict__ out)
{
    __shared__ int    s_src[8][DEG_CAP];
    __shared__ float4 s_att[8][DEG_CAP];

    const int wid  = threadIdx.x >> 5;
    const int lane = threadIdx.x & 31;
    const int n    = blockIdx.x * 8 + wid;
    if (n >= N_NODES) return;

    const int beg = rowptr[n];
    const int d   = deg[n];

    const float4 er4 = *reinterpret_cast<const float4*>(er + n * H_HEADS);

    // pass 1: exp numerators (cached in smem) + per-head denominators
    float s0 = 0.f, s1 = 0.f, s2 = 0.f, s3 = 0.f;
    for (int i = lane; i < d; i += 32) {
        int sn = __ldg(&csr_src[beg + i]);
        float4 el4 = *reinterpret_cast<const float4*>(el + sn * H_HEADS);
        float e0 = __expf(leaky(el4.x + er4.x));
        float e1 = __expf(leaky(el4.y + er4.y));
        float e2 = __expf(leaky(el4.z + er4.z));
        float e3 = __expf(leaky(el4.w + er4.w));
        s0 += e0; s1 += e1; s2 += e2; s3 += e3;
        if (i < DEG_CAP) {
            s_src[wid][i] = sn;
            s_att[wid][i] = make_float4(e0, e1, e2, e3);
        }
    }
    #pragma unroll
    for (int off = 16; off; off >>= 1) {
        s0 += __shfl_xor_sync(0xffffffffu, s0, off);
        s1 += __shfl_xor_sync(0xffffffffu, s1, off);
        s2 += __shfl_xor_sync(0xffffffffu, s2, off);
        s3 += __shfl_xor_sync(0xffffffffu, s3, off);
    }

    const int h = lane >> 3;
    const float sh   = (h == 0) ? s0 : (h == 1) ? s1 : (h == 2) ? s2 : s3;
    const float sinv = 1.f / fmaxf(sh, 1e-9f);
    const float erh  = (h == 0) ? er4.x : (h == 1) ? er4.y : (h == 2) ? er4.z : er4.w;

    // pass 2: acc = base + sum attn * z[src]; 2x unrolled, half-precision gather
    float4 acc  = *reinterpret_cast<const float4*>(hio + n * HF + lane * 4);
    float4 acc2 = make_float4(0.f, 0.f, 0.f, 0.f);
    __syncwarp();

    auto attn_of = [&](int i, int& sn) -> float {
        if (i < DEG_CAP) {
            sn = s_src[wid][i];
            float4 a4 = s_att[wid][i];
            return ((h == 0) ? a4.x : (h == 1) ? a4.y : (h == 2) ? a4.z : a4.w) * sinv;
        } else {
            sn = __ldg(&csr_src[beg + i]);
            return __expf(leaky(__ldg(&el[sn * H_HEADS + h]) + erh)) * sinv;
        }
    };

    int i = 0;
    for (; i + 2 <= d; i += 2) {
        int sa, sb;
        float aa = attn_of(i, sa);
        float ab = attn_of(i + 1, sb);
        uint2 ra = *reinterpret_cast<const uint2*>(zh + sa * HF + lane * 4);
        uint2 rb = *reinterpret_cast<const uint2*>(zh + sb * HF + lane * 4);
        float2 a01 = __half22float2(*reinterpret_cast<__half2*>(&ra.x));
        float2 a23 = __half22float2(*reinterpret_cast<__half2*>(&ra.y));
        float2 b01 = __half22float2(*reinterpret_cast<__half2*>(&rb.x));
        float2 b23 = __half22float2(*reinterpret_cast<__half2*>(&rb.y));
        acc.x  += aa * a01.x;  acc.y  += aa * a01.y;
        acc.z  += aa * a23.x;  acc.w  += aa * a23.y;
        acc2.x += ab * b01.x;  acc2.y += ab * b01.y;
        acc2.z += ab * b23.x;  acc2.w += ab * b23.y;
    }
    if (i < d) {
        int sa;
        float aa = attn_of(i, sa);
        uint2 ra = *reinterpret_cast<const uint2*>(zh + sa * HF + lane * 4);
        float2 a01 = __half22float2(*reinterpret_cast<__half2*>(&ra.x));
        float2 a23 = __half22float2(*reinterpret_cast<__half2*>(&ra.y));
        acc.x += aa * a01.x;  acc.y += aa * a01.y;
        acc.z += aa * a23.x;  acc.w += aa * a23.y;
    }
    acc.x += acc2.x; acc.y += acc2.y; acc.z += acc2.z; acc.w += acc2.w;

    if (MODE == 0) {
        // ELU here so layer-2 GEMM (and its residual) read the activated value directly
        acc.x = elu(acc.x); acc.y = elu(acc.y); acc.z = elu(acc.z); acc.w = elu(acc.w);
        *reinterpret_cast<float4*>(hio + n * HF + lane * 4) = acc;
    } else {
        // head-mean + projection: out[n] = 0.25 * sum_{h,f} acc[h][f] * Wp[f] + bp
        const int f0 = (lane & 7) * 4;
        float v = acc.x * Wp[f0] + acc.y * Wp[f0 + 1] + acc.z * Wp[f0 + 2] + acc.w * Wp[f0 + 3];
        #pragma unroll
        for (int off = 16; off; off >>= 1) v += __shfl_down_sync(0xffffffffu, v, off);
        if (lane == 0) out[n] = 0.25f * v + bp[0];
    }
}

// ---------------- launch ----------------
extern "C" void kernel_launch(void* const* d_in, const int* in_sizes, int n_in,
                              void* d_out, int out_size)
{
    const float* feats = (const float*)d_in[0];
    const int*   src   = (const int*)  d_in[1];
    const int*   dst   = (const int*)  d_in[2];
    const float* W1    = (const float*)d_in[3];
    const float* al1   = (const float*)d_in[4];
    const float* ar1   = (const float*)d_in[5];
    const float* b1    = (const float*)d_in[6];
    const float* W2    = (const float*)d_in[7];
    const float* al2   = (const float*)d_in[8];
    const float* ar2   = (const float*)d_in[9];
    const float* b2    = (const float*)d_in[10];
    const float* Wp    = (const float*)d_in[11];
    const float* bp    = (const float*)d_in[12];
    float* out = (float*)d_out;

    const int E = in_sizes[1];

    __half* zh; float *acc1, *acc2, *el, *er;
    int *deg, *rowptr, *cursor, *csr_src;
    cudaGetSymbolAddress((void**)&zh,      g_zh);
    cudaGetSymbolAddress((void**)&acc1,    g_acc1);
    cudaGetSymbolAddress((void**)&acc2,    g_acc2);
    cudaGetSymbolAddress((void**)&el,      g_el);
    cudaGetSymbolAddress((void**)&er,      g_er);
    cudaGetSymbolAddress((void**)&deg,     g_deg);
    cudaGetSymbolAddress((void**)&rowptr,  g_rowptr);
    cudaGetSymbolAddress((void**)&cursor,  g_cursor);
    cudaGetSymbolAddress((void**)&csr_src, g_csr_src);

    const int node_grid = (N_NODES + 255) / 256;
    const int edge_grid = (E + 255) / 256;
    const int gemm_grid = (N_NODES + NODES_PER_BLK - 1) / NODES_PER_BLK;
    const int agg_grid  = (N_NODES + 7) / 8;

    // ---- CSR build (by dst): 4 kernels ----
    zero_deg_kernel<<<node_grid, 256>>>(deg);
    hist_kernel    <<<edge_grid, 256>>>(dst, E, deg);
    scan_kernel    <<<1, SCAN_BLK>>>(deg, rowptr, cursor);
    fill_kernel    <<<edge_grid, 256>>>(src, dst, E, cursor, csr_src);

    // ---- layer 1 ----
    gemm_attn_kernel<<<gemm_grid, 128>>>(feats, W1, al1, ar1, b1, zh, acc1, el, er);
    gat_aggregate_kernel<0><<<agg_grid, 256>>>(rowptr, deg, csr_src, el, er, zh,
                                               acc1, Wp, bp, out);

    // ---- layer 2 (input acc1 already ELU'd) + fused head ----
    gemm_attn_kernel<<<gemm_grid, 128>>>(acc1, W2, al2, ar2, b2, zh, acc2, el, er);
    gat_aggregate_kernel<1><<<agg_grid, 256>>>(rowptr, deg, csr_src, el, er, zh,
                                               acc2, Wp, bp, out);
}

// round 4
// speedup vs baseline: 1.4987x; 1.4987x over previous
#include <cuda_runtime.h>
#include <cuda_fp16.h>

#define N_NODES 50000
#define HF 128          // H*F
#define H_HEADS 4
#define NODES_PER_BLK 32
#define E_MAX 1000000
#define DEG_CAP 128
#define SCAN_BLK 1024
#define SCAN_PER ((N_NODES + SCAN_BLK - 1) / SCAN_BLK)

// ---------------- scratch (static device globals; no allocation) ----------------
__device__ float g_z[N_NODES * HF];
__device__ float g_acc1[N_NODES * HF];   // layer-1 base -> elu(h1)
__device__ float g_acc2[N_NODES * HF];   // layer-2 base (residual + bias)
__device__ float g_el[N_NODES * H_HEADS];
__device__ float g_er[N_NODES * H_HEADS];
__device__ int   g_deg[N_NODES];
__device__ int   g_rowptr[N_NODES];
__device__ int   g_cursor[N_NODES];
__device__ int   g_csr_src[E_MAX];

__device__ __forceinline__ float leaky(float v) { return v > 0.f ? v : 0.2f * v; }
__device__ __forceinline__ float elu(float v)   { return v > 0.f ? v : (__expf(v) - 1.f); }

// ---------------- CSR build ----------------
__global__ void zero_deg_kernel(int* deg) {
    int i = blockIdx.x * blockDim.x + threadIdx.x;
    if (i < N_NODES) deg[i] = 0;
}

__global__ void hist_kernel(const int* __restrict__ dst, int E, int* __restrict__ deg) {
    int i = blockIdx.x * blockDim.x + threadIdx.x;
    if (i < E) atomicAdd(&deg[dst[i]], 1);
}

// single-block exclusive scan: thread t owns a contiguous chunk of SCAN_PER nodes
__global__ __launch_bounds__(SCAN_BLK)
void scan_kernel(const int* __restrict__ deg,
                 int* __restrict__ rowptr, int* __restrict__ cursor)
{
    __shared__ int sm[SCAN_BLK];
    const int tid = threadIdx.x;
    const int b = tid * SCAN_PER;
    const int e = min(b + SCAN_PER, N_NODES);

    int local = 0;
    for (int k = b; k < e; k++) local += deg[k];
    sm[tid] = local;
    __syncthreads();
    #pragma unroll
    for (int off = 1; off < SCAN_BLK; off <<= 1) {
        int t = (tid >= off) ? sm[tid - off] : 0;
        __syncthreads();
        sm[tid] += t;
        __syncthreads();
    }
    int run = sm[tid] - local;   // exclusive prefix
    for (int k = b; k < e; k++) {
        rowptr[k] = run;
        cursor[k] = run;
        run += deg[k];
    }
}

__global__ void fill_kernel(const int* __restrict__ src, const int* __restrict__ dst, int E,
                            int* __restrict__ cursor, int* __restrict__ csr_src) {
    int i = blockIdx.x * blockDim.x + threadIdx.x;
    if (i >= E) return;
    int pos = atomicAdd(&cursor[dst[i]], 1);
    csr_src[pos] = src[i];
}

// ---------------- K1: z = x @ W ; el/er ; base = residual + bias ----------------
__global__ __launch_bounds__(128)
void gemm_attn_kernel(const float* __restrict__ x,
                      const float* __restrict__ W,
                      const float* __restrict__ al,
                      const float* __restrict__ ar,
                      const float* __restrict__ bias,
                      float* __restrict__ z,
                      float* __restrict__ base,
                      float* __restrict__ el,
                      float* __restrict__ er)
{
    __shared__ float xs[NODES_PER_BLK * HF];  // 16 KB
    const int j  = threadIdx.x;               // 0..127 output column
    const int n0 = blockIdx.x * NODES_PER_BLK;

    #pragma unroll
    for (int nn = 0; nn < NODES_PER_BLK; nn++) {
        int n = n0 + nn;
        xs[nn * HF + j] = (n < N_NODES) ? x[n * HF + j] : 0.f;
    }
    __syncthreads();

    float sum[NODES_PER_BLK];
    #pragma unroll
    for (int nn = 0; nn < NODES_PER_BLK; nn++) sum[nn] = 0.f;

    for (int k = 0; k < HF; k += 4) {
        float w0 = W[(k + 0) * HF + j];
        float w1 = W[(k + 1) * HF + j];
        float w2 = W[(k + 2) * HF + j];
        float w3 = W[(k + 3) * HF + j];
        #pragma unroll
        for (int nn = 0; nn < NODES_PER_BLK; nn++) {
            float4 xv = *reinterpret_cast<const float4*>(&xs[nn * HF + k]);
            sum[nn] += xv.x * w0 + xv.y * w1 + xv.z * w2 + xv.w * w3;
        }
    }

    const float alj = al[j], arj = ar[j], bj = bias[j];
    const int h = j >> 5, f = j & 31;

    #pragma unroll
    for (int nn = 0; nn < NODES_PER_BLK; nn++) {
        int n = n0 + nn;
        if (n >= N_NODES) break;
        z[n * HF + j]    = sum[nn];
        base[n * HF + j] = xs[nn * HF + j] + bj;
        float pl = sum[nn] * alj;
        float pr = sum[nn] * arj;
        #pragma unroll
        for (int off = 16; off; off >>= 1) {
            pl += __shfl_down_sync(0xffffffffu, pl, off);
            pr += __shfl_down_sync(0xffffffffu, pr, off);
        }
        if (f == 0) {
            el[n * H_HEADS + h] = pl;
            er[n * H_HEADS + h] = pr;
        }
    }
}

// ---------------- fused softmax + aggregate, one warp per node, no atomics ----------------
// MODE 0: layer-1 epilogue -> elu(acc) stored to hio (becomes layer-2 input)
// MODE 1: layer-2 epilogue -> head-mean + projection, writes out[n] only
template <int MODE>
__global__ __launch_bounds__(256)
void gat_aggregate_kernel(const int* __restrict__ rowptr, const int* __restrict__ deg,
                          const int* __restrict__ csr_src,
                          const float* __restrict__ el, const float* __restrict__ er,
                          const float* __restrict__ z,
                          float* __restrict__ hio,          // base in, result out (MODE 0)
                          const float* __restrict__ Wp, const float* __restrict__ bp,
                          float* __restrict__ out)
{
    __shared__ int    s_src[8][DEG_CAP];
    __shared__ float4 s_att[8][DEG_CAP];

    const int wid  = threadIdx.x >> 5;
    const int lane = threadIdx.x & 31;
    const int n    = blockIdx.x * 8 + wid;
    if (n >= N_NODES) return;

    const int beg = rowptr[n];
    const int d   = deg[n];

    const float4 er4 = *reinterpret_cast<const float4*>(er + n * H_HEADS);

    // pass 1: exp numerators (cached in smem) + per-head denominators
    float s0 = 0.f, s1 = 0.f, s2 = 0.f, s3 = 0.f;
    for (int i = lane; i < d; i += 32) {
        int sn = __ldg(&csr_src[beg + i]);
        float4 el4 = *reinterpret_cast<const float4*>(el + sn * H_HEADS);
        float e0 = __expf(leaky(el4.x + er4.x));
        float e1 = __expf(leaky(el4.y + er4.y));
        float e2 = __expf(leaky(el4.z + er4.z));
        float e3 = __expf(leaky(el4.w + er4.w));
        s0 += e0; s1 += e1; s2 += e2; s3 += e3;
        if (i < DEG_CAP) {
            s_src[wid][i] = sn;
            s_att[wid][i] = make_float4(e0, e1, e2, e3);
        }
    }
    #pragma unroll
    for (int off = 16; off; off >>= 1) {
        s0 += __shfl_xor_sync(0xffffffffu, s0, off);
        s1 += __shfl_xor_sync(0xffffffffu, s1, off);
        s2 += __shfl_xor_sync(0xffffffffu, s2, off);
        s3 += __shfl_xor_sync(0xffffffffu, s3, off);
    }

    const int h = lane >> 3;
    const float sh   = (h == 0) ? s0 : (h == 1) ? s1 : (h == 2) ? s2 : s3;
    const float sinv = 1.f / fmaxf(sh, 1e-9f);
    const float erh  = (h == 0) ? er4.x : (h == 1) ? er4.y : (h == 2) ? er4.z : er4.w;

    // pass 2: acc = base + sum attn * z[src]  (R2-proven loop shape)
    float4 acc = *reinterpret_cast<const float4*>(hio + n * HF + lane * 4);
    __syncwarp();

    for (int i = 0; i < d; ++i) {
        int sn; float ev;
        if (i < DEG_CAP) {
            sn = s_src[wid][i];
            float4 a4 = s_att[wid][i];
            ev = (h == 0) ? a4.x : (h == 1) ? a4.y : (h == 2) ? a4.z : a4.w;
        } else {
            sn = __ldg(&csr_src[beg + i]);
            ev = __expf(leaky(__ldg(&el[sn * H_HEADS + h]) + erh));
        }
        float a = ev * sinv;
        float4 zv = *reinterpret_cast<const float4*>(z + sn * HF + lane * 4);
        acc.x += a * zv.x;
        acc.y += a * zv.y;
        acc.z += a * zv.z;
        acc.w += a * zv.w;
    }

    if (MODE == 0) {
        // ELU here so layer-2 GEMM (and its residual) read the activated value directly
        acc.x = elu(acc.x); acc.y = elu(acc.y); acc.z = elu(acc.z); acc.w = elu(acc.w);
        *reinterpret_cast<float4*>(hio + n * HF + lane * 4) = acc;
    } else {
        // head-mean + projection: out[n] = 0.25 * sum_{h,f} acc[h][f] * Wp[f] + bp
        const int f0 = (lane & 7) * 4;
        float v = acc.x * Wp[f0] + acc.y * Wp[f0 + 1] + acc.z * Wp[f0 + 2] + acc.w * Wp[f0 + 3];
        #pragma unroll
        for (int off = 16; off; off >>= 1) v += __shfl_down_sync(0xffffffffu, v, off);
        if (lane == 0) out[n] = 0.25f * v + bp[0];
    }
}

// ---------------- launch ----------------
extern "C" void kernel_launch(void* const* d_in, const int* in_sizes, int n_in,
                              void* d_out, int out_size)
{
    const float* feats = (const float*)d_in[0];
    const int*   src   = (const int*)  d_in[1];
    const int*   dst   = (const int*)  d_in[2];
    const float* W1    = (const float*)d_in[3];
    const float* al1   = (const float*)d_in[4];
    const float* ar1   = (const float*)d_in[5];
    const float* b1    = (const float*)d_in[6];
    const float* W2    = (const float*)d_in[7];
    const float* al2   = (const float*)d_in[8];
    const float* ar2   = (const float*)d_in[9];
    const float* b2    = (const float*)d_in[10];
    const float* Wp    = (const float*)d_in[11];
    const float* bp    = (const float*)d_in[12];
    float* out = (float*)d_out;

    const int E = in_sizes[1];

    float *z, *acc1, *acc2, *el, *er;
    int *deg, *rowptr, *cursor, *csr_src;
    cudaGetSymbolAddress((void**)&z,       g_z);
    cudaGetSymbolAddress((void**)&acc1,    g_acc1);
    cudaGetSymbolAddress((void**)&acc2,    g_acc2);
    cudaGetSymbolAddress((void**)&el,      g_el);
    cudaGetSymbolAddress((void**)&er,      g_er);
    cudaGetSymbolAddress((void**)&deg,     g_deg);
    cudaGetSymbolAddress((void**)&rowptr,  g_rowptr);
    cudaGetSymbolAddress((void**)&cursor,  g_cursor);
    cudaGetSymbolAddress((void**)&csr_src, g_csr_src);

    const int node_grid = (N_NODES + 255) / 256;
    const int edge_grid = (E + 255) / 256;
    const int gemm_grid = (N_NODES + NODES_PER_BLK - 1) / NODES_PER_BLK;
    const int agg_grid  = (N_NODES + 7) / 8;

    // ---- CSR build (by dst): 4 kernels ----
    zero_deg_kernel<<<node_grid, 256>>>(deg);
    hist_kernel    <<<edge_grid, 256>>>(dst, E, deg);
    scan_kernel    <<<1, SCAN_BLK>>>(deg, rowptr, cursor);
    fill_kernel    <<<edge_grid, 256>>>(src, dst, E, cursor, csr_src);

    // ---- layer 1 ----
    gemm_attn_kernel<<<gemm_grid, 128>>>(feats, W1, al1, ar1, b1, z, acc1, el, er);
    gat_aggregate_kernel<0><<<agg_grid, 256>>>(rowptr, deg, csr_src, el, er, z,
                                               acc1, Wp, bp, out);

    // ---- layer 2 (input acc1 already ELU'd) + fused head ----
    gemm_attn_kernel<<<gemm_grid, 128>>>(acc1, W2, al2, ar2, b2, z, acc2, el, er);
    gat_aggregate_kernel<1><<<agg_grid, 256>>>(rowptr, deg, csr_src, el, er, z,
                                               acc2, Wp, bp, out);
}

// round 5
// speedup vs baseline: 1.9853x; 1.3246x over previous
#include <cuda_runtime.h>
#include <cuda_fp16.h>

#define N_NODES 50000
#define HF 128          // H*F
#define H_HEADS 4
#define NODES_PER_BLK 32
#define E_MAX 1000000
#define DEG_CAP 128
#define SCAN_BLK 1024
#define N_SCAN_BLKS ((N_NODES + SCAN_BLK - 1) / SCAN_BLK)

// ---------------- packed f32x2 helpers (sm_103a) ----------------
#define PACK_F32X2(out, lo, hi) \
    asm("mov.b64 %0, {%1, %2};" : "=l"(out) : "f"(lo), "f"(hi))
#define UNPACK_F32X2(lo, hi, in) \
    asm("mov.b64 {%0, %1}, %2;" : "=f"(lo), "=f"(hi) : "l"(in))
#define FMA_F32X2(d, a, b, c) \
    asm("fma.rn.f32x2 %0, %1, %2, %3;" : "=l"(d) : "l"(a), "l"(b), "l"(c))

// ---------------- scratch (static device globals; no allocation) ----------------
__device__ float g_z[N_NODES * HF];
__device__ float g_acc1[N_NODES * HF];   // layer-1 base -> elu(h1)
__device__ float g_acc2[N_NODES * HF];   // layer-2 base (residual + bias)
__device__ float g_el[N_NODES * H_HEADS];
__device__ float g_er[N_NODES * H_HEADS];
__device__ int   g_deg[N_NODES];
__device__ int   g_rowptr[N_NODES];
__device__ int   g_cursor[N_NODES];
__device__ int   g_incl[N_NODES];
__device__ int   g_bsum[N_SCAN_BLKS];
__device__ int   g_boff[N_SCAN_BLKS];
__device__ int   g_csr_src[E_MAX];

__device__ __forceinline__ float leaky(float v) { return v > 0.f ? v : 0.2f * v; }
__device__ __forceinline__ float elu(float v)   { return v > 0.f ? v : (__expf(v) - 1.f); }

// ---------------- CSR build (R2-proven parallel version) ----------------
__global__ void zero_deg_kernel(int* deg) {
    int i = blockIdx.x * blockDim.x + threadIdx.x;
    if (i < N_NODES) deg[i] = 0;
}

__global__ void hist_kernel(const int* __restrict__ dst, int E, int* __restrict__ deg) {
    int i = blockIdx.x * blockDim.x + threadIdx.x;
    if (i < E) atomicAdd(&deg[dst[i]], 1);
}

__global__ __launch_bounds__(SCAN_BLK)
void scan1_kernel(const int* __restrict__ deg, int* __restrict__ incl, int* __restrict__ bsum) {
    __shared__ int sm[SCAN_BLK];
    int tid = threadIdx.x;
    int i = blockIdx.x * SCAN_BLK + tid;
    int v = (i < N_NODES) ? deg[i] : 0;
    sm[tid] = v;
    __syncthreads();
    #pragma unroll
    for (int off = 1; off < SCAN_BLK; off <<= 1) {
        int t = (tid >= off) ? sm[tid - off] : 0;
        __syncthreads();
        sm[tid] += t;
        __syncthreads();
    }
    if (i < N_NODES) incl[i] = sm[tid];
    if (tid == SCAN_BLK - 1) bsum[blockIdx.x] = sm[tid];
}

__global__ void scan2_kernel(const int* __restrict__ bsum, int* __restrict__ boff) {
    __shared__ int sm[64];
    int tid = threadIdx.x;   // blockDim = 64 >= N_SCAN_BLKS
    sm[tid] = (tid < N_SCAN_BLKS) ? bsum[tid] : 0;
    __syncthreads();
    #pragma unroll
    for (int off = 1; off < 64; off <<= 1) {
        int t = (tid >= off) ? sm[tid - off] : 0;
        __syncthreads();
        sm[tid] += t;
        __syncthreads();
    }
    if (tid < N_SCAN_BLKS) boff[tid] = sm[tid] - bsum[tid];  // exclusive
}

__global__ void scan3_kernel(const int* __restrict__ incl, const int* __restrict__ deg,
                             const int* __restrict__ boff,
                             int* __restrict__ rowptr, int* __restrict__ cursor) {
    int i = blockIdx.x * blockDim.x + threadIdx.x;
    if (i >= N_NODES) return;
    int excl = incl[i] - deg[i] + boff[i / SCAN_BLK];
    rowptr[i] = excl;
    cursor[i] = excl;
}

__global__ void fill_kernel(const int* __restrict__ src, const int* __restrict__ dst, int E,
                            int* __restrict__ cursor, int* __restrict__ csr_src) {
    int i = blockIdx.x * blockDim.x + threadIdx.x;
    if (i >= E) return;
    int pos = atomicAdd(&cursor[dst[i]], 1);
    csr_src[pos] = src[i];
}

// ---------------- K1: z = x @ W via packed f32x2 ; el/er ; base = residual + bias -------
// 128 threads (thread j = output column), 32 nodes per block, node pairs packed in f32x2.
__global__ __launch_bounds__(128)
void gemm_attn_kernel(const float* __restrict__ x,
                      const float* __restrict__ W,
                      const float* __restrict__ al,
                      const float* __restrict__ ar,
                      const float* __restrict__ bias,
                      float* __restrict__ z,
                      float* __restrict__ base,
                      float* __restrict__ el,
                      float* __restrict__ er)
{
    // xs2[k][p] = { x[node 2p][k], x[node 2p+1][k] } ; padded row (17) to break bank conflicts
    __shared__ float2 xs2[HF][17];   // ~17.4 KB
    const int j  = threadIdx.x;      // 0..127 output column
    const int n0 = blockIdx.x * NODES_PER_BLK;
    const float bj = bias[j];

    #pragma unroll
    for (int nn = 0; nn < NODES_PER_BLK; nn++) {
        int n = n0 + nn;
        float xv = 0.f;
        if (n < N_NODES) {
            xv = x[n * HF + j];
            base[n * HF + j] = xv + bj;       // residual + bias, written up front
        }
        reinterpret_cast<float*>(&xs2[j][nn >> 1])[nn & 1] = xv;
    }
    __syncthreads();

    unsigned long long acc[NODES_PER_BLK / 2];
    #pragma unroll
    for (int p = 0; p < NODES_PER_BLK / 2; p++) acc[p] = 0ull;  // {0.f, 0.f}

    for (int k = 0; k < HF; k += 2) {
        float w0 = W[(k + 0) * HF + j];
        float w1 = W[(k + 1) * HF + j];
        unsigned long long w0p, w1p;
        PACK_F32X2(w0p, w0, w0);
        PACK_F32X2(w1p, w1, w1);
        #pragma unroll
        for (int p = 0; p < NODES_PER_BLK / 2; p++) {
            unsigned long long x0 = *reinterpret_cast<const unsigned long long*>(&xs2[k + 0][p]);
            unsigned long long x1 = *reinterpret_cast<const unsigned long long*>(&xs2[k + 1][p]);
            FMA_F32X2(acc[p], x0, w0p, acc[p]);
            FMA_F32X2(acc[p], x1, w1p, acc[p]);
        }
    }

    const float alj = al[j], arj = ar[j];
    const int h = j >> 5, f = j & 31;

    #pragma unroll
    for (int p = 0; p < NODES_PER_BLK / 2; p++) {
        float slo, shi;
        UNPACK_F32X2(slo, shi, acc[p]);
        #pragma unroll
        for (int q = 0; q < 2; q++) {
            int nn = 2 * p + q;
            int n = n0 + nn;
            if (n >= N_NODES) break;      // uniform across warp
            float s = q ? shi : slo;
            z[n * HF + j] = s;
            float pl = s * alj;
            float pr = s * arj;
            #pragma unroll
            for (int off = 16; off; off >>= 1) {
                pl += __shfl_down_sync(0xffffffffu, pl, off);
                pr += __shfl_down_sync(0xffffffffu, pr, off);
            }
            if (f == 0) {
                el[n * H_HEADS + h] = pl;
                er[n * H_HEADS + h] = pr;
            }
        }
    }
}

// ---------------- fused softmax + aggregate, one warp per node, no atomics ----------------
// MODE 0: layer-1 epilogue -> elu(acc) stored to hio (becomes layer-2 input)
// MODE 1: layer-2 epilogue -> head-mean + projection, writes out[n] only
template <int MODE>
__global__ __launch_bounds__(256)
void gat_aggregate_kernel(const int* __restrict__ rowptr, const int* __restrict__ deg,
                          const int* __restrict__ csr_src,
                          const float* __restrict__ el, const float* __restrict__ er,
                          const float* __restrict__ z,
                          float* __restrict__ hio,          // base in, result out (MODE 0)
                          const float* __restrict__ Wp, const float* __restrict__ bp,
                          float* __restrict__ out)
{
    __shared__ int    s_src[8][DEG_CAP];
    __shared__ float4 s_att[8][DEG_CAP];

    const int wid  = threadIdx.x >> 5;
    const int lane = threadIdx.x & 31;
    const int n    = blockIdx.x * 8 + wid;
    if (n >= N_NODES) return;

    const int beg = rowptr[n];
    const int d   = deg[n];

    const float4 er4 = *reinterpret_cast<const float4*>(er + n * H_HEADS);

    // pass 1: exp numerators (cached in smem) + per-head denominators
    float s0 = 0.f, s1 = 0.f, s2 = 0.f, s3 = 0.f;
    for (int i = lane; i < d; i += 32) {
        int sn = __ldg(&csr_src[beg + i]);
        float4 el4 = *reinterpret_cast<const float4*>(el + sn * H_HEADS);
        float e0 = __expf(leaky(el4.x + er4.x));
        float e1 = __expf(leaky(el4.y + er4.y));
        float e2 = __expf(leaky(el4.z + er4.z));
        float e3 = __expf(leaky(el4.w + er4.w));
        s0 += e0; s1 += e1; s2 += e2; s3 += e3;
        if (i < DEG_CAP) {
            s_src[wid][i] = sn;
            s_att[wid][i] = make_float4(e0, e1, e2, e3);
        }
    }
    #pragma unroll
    for (int off = 16; off; off >>= 1) {
        s0 += __shfl_xor_sync(0xffffffffu, s0, off);
        s1 += __shfl_xor_sync(0xffffffffu, s1, off);
        s2 += __shfl_xor_sync(0xffffffffu, s2, off);
        s3 += __shfl_xor_sync(0xffffffffu, s3, off);
    }

    const int h = lane >> 3;
    const float sh   = (h == 0) ? s0 : (h == 1) ? s1 : (h == 2) ? s2 : s3;
    const float sinv = 1.f / fmaxf(sh, 1e-9f);
    const float erh  = (h == 0) ? er4.x : (h == 1) ? er4.y : (h == 2) ? er4.z : er4.w;

    // pass 2: acc = base + sum attn * z[src]  (R2-proven loop shape)
    float4 acc = *reinterpret_cast<const float4*>(hio + n * HF + lane * 4);
    __syncwarp();

    for (int i = 0; i < d; ++i) {
        int sn; float ev;
        if (i < DEG_CAP) {
            sn = s_src[wid][i];
            float4 a4 = s_att[wid][i];
            ev = (h == 0) ? a4.x : (h == 1) ? a4.y : (h == 2) ? a4.z : a4.w;
        } else {
            sn = __ldg(&csr_src[beg + i]);
            ev = __expf(leaky(__ldg(&el[sn * H_HEADS + h]) + erh));
        }
        float a = ev * sinv;
        float4 zv = *reinterpret_cast<const float4*>(z + sn * HF + lane * 4);
        acc.x += a * zv.x;
        acc.y += a * zv.y;
        acc.z += a * zv.z;
        acc.w += a * zv.w;
    }

    if (MODE == 0) {
        // ELU here so layer-2 GEMM (and its residual) read the activated value directly
        acc.x = elu(acc.x); acc.y = elu(acc.y); acc.z = elu(acc.z); acc.w = elu(acc.w);
        *reinterpret_cast<float4*>(hio + n * HF + lane * 4) = acc;
    } else {
        // head-mean + projection: out[n] = 0.25 * sum_{h,f} acc[h][f] * Wp[f] + bp
        const int f0 = (lane & 7) * 4;
        float v = acc.x * Wp[f0] + acc.y * Wp[f0 + 1] + acc.z * Wp[f0 + 2] + acc.w * Wp[f0 + 3];
        #pragma unroll
        for (int off = 16; off; off >>= 1) v += __shfl_down_sync(0xffffffffu, v, off);
        if (lane == 0) out[n] = 0.25f * v + bp[0];
    }
}

// ---------------- launch ----------------
extern "C" void kernel_launch(void* const* d_in, const int* in_sizes, int n_in,
                              void* d_out, int out_size)
{
    const float* feats = (const float*)d_in[0];
    const int*   src   = (const int*)  d_in[1];
    const int*   dst   = (const int*)  d_in[2];
    const float* W1    = (const float*)d_in[3];
    const float* al1   = (const float*)d_in[4];
    const float* ar1   = (const float*)d_in[5];
    const float* b1    = (const float*)d_in[6];
    const float* W2    = (const float*)d_in[7];
    const float* al2   = (const float*)d_in[8];
    const float* ar2   = (const float*)d_in[9];
    const float* b2    = (const float*)d_in[10];
    const float* Wp    = (const float*)d_in[11];
    const float* bp    = (const float*)d_in[12];
    float* out = (float*)d_out;

    const int E = in_sizes[1];

    float *z, *acc1, *acc2, *el, *er;
    int *deg, *rowptr, *cursor, *incl, *bsum, *boff, *csr_src;
    cudaGetSymbolAddress((void**)&z,       g_z);
    cudaGetSymbolAddress((void**)&acc1,    g_acc1);
    cudaGetSymbolAddress((void**)&acc2,    g_acc2);
    cudaGetSymbolAddress((void**)&el,      g_el);
    cudaGetSymbolAddress((void**)&er,      g_er);
    cudaGetSymbolAddress((void**)&deg,     g_deg);
    cudaGetSymbolAddress((void**)&rowptr,  g_rowptr);
    cudaGetSymbolAddress((void**)&cursor,  g_cursor);
    cudaGetSymbolAddress((void**)&incl,    g_incl);
    cudaGetSymbolAddress((void**)&bsum,    g_bsum);
    cudaGetSymbolAddress((void**)&boff,    g_boff);
    cudaGetSymbolAddress((void**)&csr_src, g_csr_src);

    const int node_grid = (N_NODES + 255) / 256;
    const int edge_grid = (E + 255) / 256;
    const int gemm_grid = (N_NODES + NODES_PER_BLK - 1) / NODES_PER_BLK;
    const int agg_grid  = (N_NODES + 7) / 8;

    // ---- CSR build (by dst): parallel 3-stage scan (R2-proven) ----
    zero_deg_kernel<<<node_grid, 256>>>(deg);
    hist_kernel    <<<edge_grid, 256>>>(dst, E, deg);
    scan1_kernel   <<<N_SCAN_BLKS, SCAN_BLK>>>(deg, incl, bsum);
    scan2_kernel   <<<1, 64>>>(bsum, boff);
    scan3_kernel   <<<node_grid, 256>>>(incl, deg, boff, rowptr, cursor);
    fill_kernel    <<<edge_grid, 256>>>(src, dst, E, cursor, csr_src);

    // ---- layer 1 ----
    gemm_attn_kernel<<<gemm_grid, 128>>>(feats, W1, al1, ar1, b1, z, acc1, el, er);
    gat_aggregate_kernel<0><<<agg_grid, 256>>>(rowptr, deg, csr_src, el, er, z,
                                               acc1, Wp, bp, out);

    // ---- layer 2 (input acc1 already ELU'd) + fused head ----
    gemm_attn_kernel<<<gemm_grid, 128>>>(acc1, W2, al2, ar2, b2, z, acc2, el, er);
    gat_aggregate_kernel<1><<<agg_grid, 256>>>(rowptr, deg, csr_src, el, er, z,
                                               acc2, Wp, bp, out);
}

// round 6
// speedup vs baseline: 2.2203x; 1.1184x over previous
#include <cuda_runtime.h>
#include <cuda_fp16.h>

#define N_NODES 50000
#define HF 128          // H*F
#define H_HEADS 4
#define NODES_PER_BLK 32
#define E_MAX 1000000
#define SCAN_BLK 1024
#define N_SCAN_BLKS ((N_NODES + SCAN_BLK - 1) / SCAN_BLK)

// ---------------- packed f32x2 helpers (sm_103a) ----------------
#define PACK_F32X2(out, lo, hi) \
    asm("mov.b64 %0, {%1, %2};" : "=l"(out) : "f"(lo), "f"(hi))
#define UNPACK_F32X2(lo, hi, in) \
    asm("mov.b64 {%0, %1}, %2;" : "=f"(lo), "=f"(hi) : "l"(in))
#define FMA_F32X2(d, a, b, c) \
    asm("fma.rn.f32x2 %0, %1, %2, %3;" : "=l"(d) : "l"(a), "l"(b), "l"(c))

// ---------------- scratch (static device globals; no allocation) ----------------
__device__ float g_z[N_NODES * HF];
__device__ float g_acc1[N_NODES * HF];   // layer-1 base -> elu(h1)
__device__ float g_acc2[N_NODES * HF];   // layer-2 base (residual + bias)
__device__ float g_el[N_NODES * H_HEADS];
__device__ float g_er[N_NODES * H_HEADS];
__device__ int   g_deg[N_NODES];
__device__ int   g_rowptr[N_NODES];
__device__ int   g_cursor[N_NODES];
__device__ int   g_incl[N_NODES];
__device__ int   g_bsum[N_SCAN_BLKS];
__device__ int   g_boff[N_SCAN_BLKS];
__device__ int   g_csr_src[E_MAX];

__device__ __forceinline__ float leaky(float v) { return v > 0.f ? v : 0.2f * v; }
__device__ __forceinline__ float elu(float v)   { return v > 0.f ? v : (__expf(v) - 1.f); }

// ---------------- CSR build (R2/R5-proven parallel version) ----------------
__global__ void zero_deg_kernel(int* deg) {
    int i = blockIdx.x * blockDim.x + threadIdx.x;
    if (i < N_NODES) deg[i] = 0;
}

__global__ void hist_kernel(const int* __restrict__ dst, int E, int* __restrict__ deg) {
    int i = blockIdx.x * blockDim.x + threadIdx.x;
    if (i < E) atomicAdd(&deg[dst[i]], 1);
}

__global__ __launch_bounds__(SCAN_BLK)
void scan1_kernel(const int* __restrict__ deg, int* __restrict__ incl, int* __restrict__ bsum) {
    __shared__ int sm[SCAN_BLK];
    int tid = threadIdx.x;
    int i = blockIdx.x * SCAN_BLK + tid;
    int v = (i < N_NODES) ? deg[i] : 0;
    sm[tid] = v;
    __syncthreads();
    #pragma unroll
    for (int off = 1; off < SCAN_BLK; off <<= 1) {
        int t = (tid >= off) ? sm[tid - off] : 0;
        __syncthreads();
        sm[tid] += t;
        __syncthreads();
    }
    if (i < N_NODES) incl[i] = sm[tid];
    if (tid == SCAN_BLK - 1) bsum[blockIdx.x] = sm[tid];
}

__global__ void scan2_kernel(const int* __restrict__ bsum, int* __restrict__ boff) {
    __shared__ int sm[64];
    int tid = threadIdx.x;   // blockDim = 64 >= N_SCAN_BLKS
    sm[tid] = (tid < N_SCAN_BLKS) ? bsum[tid] : 0;
    __syncthreads();
    #pragma unroll
    for (int off = 1; off < 64; off <<= 1) {
        int t = (tid >= off) ? sm[tid - off] : 0;
        __syncthreads();
        sm[tid] += t;
        __syncthreads();
    }
    if (tid < N_SCAN_BLKS) boff[tid] = sm[tid] - bsum[tid];  // exclusive
}

__global__ void scan3_kernel(const int* __restrict__ incl, const int* __restrict__ deg,
                             const int* __restrict__ boff,
                             int* __restrict__ rowptr, int* __restrict__ cursor) {
    int i = blockIdx.x * blockDim.x + threadIdx.x;
    if (i >= N_NODES) return;
    int excl = incl[i] - deg[i] + boff[i / SCAN_BLK];
    rowptr[i] = excl;
    cursor[i] = excl;
}

__global__ void fill_kernel(const int* __restrict__ src, const int* __restrict__ dst, int E,
                            int* __restrict__ cursor, int* __restrict__ csr_src) {
    int i = blockIdx.x * blockDim.x + threadIdx.x;
    if (i >= E) return;
    int pos = atomicAdd(&cursor[dst[i]], 1);
    csr_src[pos] = src[i];
}

// ---------------- K1: z = x @ W via packed f32x2 ; el/er ; base = residual + bias -------
__global__ __launch_bounds__(128)
void gemm_attn_kernel(const float* __restrict__ x,
                      const float* __restrict__ W,
                      const float* __restrict__ al,
                      const float* __restrict__ ar,
                      const float* __restrict__ bias,
                      float* __restrict__ z,
                      float* __restrict__ base,
                      float* __restrict__ el,
                      float* __restrict__ er)
{
    // xs2[k][p] = { x[node 2p][k], x[node 2p+1][k] } ; padded row (17) to break bank conflicts
    __shared__ float2 xs2[HF][17];   // ~17.4 KB
    const int j  = threadIdx.x;      // 0..127 output column
    const int n0 = blockIdx.x * NODES_PER_BLK;
    const float bj = bias[j];

    #pragma unroll
    for (int nn = 0; nn < NODES_PER_BLK; nn++) {
        int n = n0 + nn;
        float xv = 0.f;
        if (n < N_NODES) {
            xv = x[n * HF + j];
            base[n * HF + j] = xv + bj;       // residual + bias, written up front
        }
        reinterpret_cast<float*>(&xs2[j][nn >> 1])[nn & 1] = xv;
    }
    __syncthreads();

    unsigned long long acc[NODES_PER_BLK / 2];
    #pragma unroll
    for (int p = 0; p < NODES_PER_BLK / 2; p++) acc[p] = 0ull;  // {0.f, 0.f}

    for (int k = 0; k < HF; k += 2) {
        float w0 = W[(k + 0) * HF + j];
        float w1 = W[(k + 1) * HF + j];
        unsigned long long w0p, w1p;
        PACK_F32X2(w0p, w0, w0);
        PACK_F32X2(w1p, w1, w1);
        #pragma unroll
        for (int p = 0; p < NODES_PER_BLK / 2; p++) {
            unsigned long long x0 = *reinterpret_cast<const unsigned long long*>(&xs2[k + 0][p]);
            unsigned long long x1 = *reinterpret_cast<const unsigned long long*>(&xs2[k + 1][p]);
            FMA_F32X2(acc[p], x0, w0p, acc[p]);
            FMA_F32X2(acc[p], x1, w1p, acc[p]);
        }
    }

    const float alj = al[j], arj = ar[j];
    const int h = j >> 5, f = j & 31;

    #pragma unroll
    for (int p = 0; p < NODES_PER_BLK / 2; p++) {
        float slo, shi;
        UNPACK_F32X2(slo, shi, acc[p]);
        #pragma unroll
        for (int q = 0; q < 2; q++) {
            int nn = 2 * p + q;
            int n = n0 + nn;
            if (n >= N_NODES) break;      // uniform across warp
            float s = q ? shi : slo;
            z[n * HF + j] = s;
            float pl = s * alj;
            float pr = s * arj;
            #pragma unroll
            for (int off = 16; off; off >>= 1) {
                pl += __shfl_down_sync(0xffffffffu, pl, off);
                pr += __shfl_down_sync(0xffffffffu, pr, off);
            }
            if (f == 0) {
                el[n * H_HEADS + h] = pl;
                er[n * H_HEADS + h] = pr;
            }
        }
    }
}

// ---------------- single-pass softmax-free aggregate, one warp per node -----------------
// h_n = base_n + (sum_i e_i * z_{src_i}) / (sum_i e_i), computed unnormalized then scaled.
// Every lane of head h accumulates the identical denominator -> no reduction at all.
// MODE 0: layer-1 epilogue -> elu(acc) stored to hio (becomes layer-2 input)
// MODE 1: layer-2 epilogue -> head-mean + projection, writes out[n] only
template <int MODE>
__global__ __launch_bounds__(256)
void gat_aggregate_kernel(const int* __restrict__ rowptr, const int* __restrict__ deg,
                          const int* __restrict__ csr_src,
                          const float* __restrict__ el, const float* __restrict__ er,
                          const float* __restrict__ z,
                          float* __restrict__ hio,          // base in, result out (MODE 0)
                          const float* __restrict__ Wp, const float* __restrict__ bp,
                          float* __restrict__ out)
{
    const int wid  = threadIdx.x >> 5;
    const int lane = threadIdx.x & 31;
    const int n    = blockIdx.x * 8 + wid;
    if (n >= N_NODES) return;

    const int beg = rowptr[n];
    const int d   = deg[n];
    const int h   = lane >> 3;

    const float erh = __ldg(&er[n * H_HEADS + h]);

    float  s   = 0.f;
    float4 acc = make_float4(0.f, 0.f, 0.f, 0.f);

    for (int i = 0; i < d; ++i) {
        int   sn = __ldg(&csr_src[beg + i]);                       // warp-uniform
        float ev = __expf(leaky(__ldg(&el[sn * H_HEADS + h]) + erh));
        float4 zv = *reinterpret_cast<const float4*>(z + sn * HF + lane * 4);
        s     += ev;
        acc.x += ev * zv.x;
        acc.y += ev * zv.y;
        acc.z += ev * zv.z;
        acc.w += ev * zv.w;
    }

    const float sinv = 1.f / fmaxf(s, 1e-9f);
    float4 base = *reinterpret_cast<const float4*>(hio + n * HF + lane * 4);
    acc.x = base.x + acc.x * sinv;
    acc.y = base.y + acc.y * sinv;
    acc.z = base.z + acc.z * sinv;
    acc.w = base.w + acc.w * sinv;

    if (MODE == 0) {
        // ELU here so layer-2 GEMM (and its residual) read the activated value directly
        acc.x = elu(acc.x); acc.y = elu(acc.y); acc.z = elu(acc.z); acc.w = elu(acc.w);
        *reinterpret_cast<float4*>(hio + n * HF + lane * 4) = acc;
    } else {
        // head-mean + projection: out[n] = 0.25 * sum_{h,f} acc[h][f] * Wp[f] + bp
        const int f0 = (lane & 7) * 4;
        float v = acc.x * Wp[f0] + acc.y * Wp[f0 + 1] + acc.z * Wp[f0 + 2] + acc.w * Wp[f0 + 3];
        #pragma unroll
        for (int off = 16; off; off >>= 1) v += __shfl_down_sync(0xffffffffu, v, off);
        if (lane == 0) out[n] = 0.25f * v + bp[0];
    }
}

// ---------------- launch ----------------
extern "C" void kernel_launch(void* const* d_in, const int* in_sizes, int n_in,
                              void* d_out, int out_size)
{
    const float* feats = (const float*)d_in[0];
    const int*   src   = (const int*)  d_in[1];
    const int*   dst   = (const int*)  d_in[2];
    const float* W1    = (const float*)d_in[3];
    const float* al1   = (const float*)d_in[4];
    const float* ar1   = (const float*)d_in[5];
    const float* b1    = (const float*)d_in[6];
    const float* W2    = (const float*)d_in[7];
    const float* al2   = (const float*)d_in[8];
    const float* ar2   = (const float*)d_in[9];
    const float* b2    = (const float*)d_in[10];
    const float* Wp    = (const float*)d_in[11];
    const float* bp    = (const float*)d_in[12];
    float* out = (float*)d_out;

    const int E = in_sizes[1];

    float *z, *acc1, *acc2, *el, *er;
    int *deg, *rowptr, *cursor, *incl, *bsum, *boff, *csr_src;
    cudaGetSymbolAddress((void**)&z,       g_z);
    cudaGetSymbolAddress((void**)&acc1,    g_acc1);
    cudaGetSymbolAddress((void**)&acc2,    g_acc2);
    cudaGetSymbolAddress((void**)&el,      g_el);
    cudaGetSymbolAddress((void**)&er,      g_er);
    cudaGetSymbolAddress((void**)&deg,     g_deg);
    cudaGetSymbolAddress((void**)&rowptr,  g_rowptr);
    cudaGetSymbolAddress((void**)&cursor,  g_cursor);
    cudaGetSymbolAddress((void**)&incl,    g_incl);
    cudaGetSymbolAddress((void**)&bsum,    g_bsum);
    cudaGetSymbolAddress((void**)&boff,    g_boff);
    cudaGetSymbolAddress((void**)&csr_src, g_csr_src);

    const int node_grid = (N_NODES + 255) / 256;
    const int edge_grid = (E + 255) / 256;
    const int gemm_grid = (N_NODES + NODES_PER_BLK - 1) / NODES_PER_BLK;
    const int agg_grid  = (N_NODES + 7) / 8;

    // ---- CSR build (by dst): parallel 3-stage scan ----
    zero_deg_kernel<<<node_grid, 256>>>(deg);
    hist_kernel    <<<edge_grid, 256>>>(dst, E, deg);
    scan1_kernel   <<<N_SCAN_BLKS, SCAN_BLK>>>(deg, incl, bsum);
    scan2_kernel   <<<1, 64>>>(bsum, boff);
    scan3_kernel   <<<node_grid, 256>>>(incl, deg, boff, rowptr, cursor);
    fill_kernel    <<<edge_grid, 256>>>(src, dst, E, cursor, csr_src);

    // ---- layer 1 ----
    gemm_attn_kernel<<<gemm_grid, 128>>>(feats, W1, al1, ar1, b1, z, acc1, el, er);
    gat_aggregate_kernel<0><<<agg_grid, 256>>>(rowptr, deg, csr_src, el, er, z,
                                               acc1, Wp, bp, out);

    // ---- layer 2 (input acc1 already ELU'd) + fused head ----
    gemm_attn_kernel<<<gemm_grid, 128>>>(acc1, W2, al2, ar2, b2, z, acc2, el, er);
    gat_aggregate_kernel<1><<<agg_grid, 256>>>(rowptr, deg, csr_src, el, er, z,
                                               acc2, Wp, bp, out);
}